// round 17
// baseline (speedup 1.0000x reference)
#include <cuda_runtime.h>
#include <cuda_bf16.h>
#include <cstdint>

// ---------------------------------------------------------------------------
// MultiHeadAttention: B=2, S=2048, D=1024, H=16, d_k=64
// Round 17 (= six-times-audited R12; broker timeouts): projections on
// mma.sync bf16x2 split HMMA. Attention phase 1 (QK^T) on mma.sync with the
// same fragment maps; projection epilogue emits split-bf16 Q/K. Softmax,
// weights write, PV phase 3, reduction byte-identical to passing R4.
// ---------------------------------------------------------------------------

#define B_SZ    2
#define S_LEN   2048
#define D_MODEL 1024
#define NH      16
#define DK      64
#define MROWS   (B_SZ * S_LEN)            // 4096

// fp32 scratch: gV(z=2 output), gC ; gQ/gK slots kept for layout simplicity
__device__ float g_f32[4u * MROWS * D_MODEL];
// bf16 split scratch
__device__ __nv_bfloat16 g_a_h[3u * MROWS * D_MODEL];
__device__ __nv_bfloat16 g_a_l[3u * MROWS * D_MODEL];
__device__ __nv_bfloat16 g_w_h[4u * D_MODEL * D_MODEL];   // transposed [N][K]
__device__ __nv_bfloat16 g_w_l[4u * D_MODEL * D_MODEL];
__device__ __nv_bfloat16 g_c_h[1u * MROWS * D_MODEL];
__device__ __nv_bfloat16 g_c_l[1u * MROWS * D_MODEL];
// split Q/K produced by projection epilogue
__device__ __nv_bfloat16 g_q_h[1u * MROWS * D_MODEL];
__device__ __nv_bfloat16 g_q_l[1u * MROWS * D_MODEL];
__device__ __nv_bfloat16 g_k_h[1u * MROWS * D_MODEL];
__device__ __nv_bfloat16 g_k_l[1u * MROWS * D_MODEL];

// ========================= PTX helpers (compute_80-safe) ===================
__device__ __forceinline__ uint32_t smem_to_u32(const void* p) {
    uint32_t a;
    asm("{ .reg .u64 t; cvta.to.shared.u64 t, %1; cvt.u32.u64 %0, t; }"
        : "=r"(a) : "l"(p));
    return a;
}

__device__ __forceinline__ void cp_async16(uint32_t saddr, const void* g) {
    asm volatile("cp.async.cg.shared.global [%0], [%1], 16;"
                 :: "r"(saddr), "l"(g));
}
__device__ __forceinline__ void cp_commit() {
    asm volatile("cp.async.commit_group;" ::: "memory");
}
template <int N> __device__ __forceinline__ void cp_wait() {
    asm volatile("cp.async.wait_group %0;" :: "n"(N) : "memory");
}

__device__ __forceinline__ void ldsm4(uint32_t* r, uint32_t addr) {
    asm volatile("ldmatrix.sync.aligned.m8n8.x4.shared.b16 {%0,%1,%2,%3}, [%4];"
                 : "=r"(r[0]), "=r"(r[1]), "=r"(r[2]), "=r"(r[3]) : "r"(addr));
}
__device__ __forceinline__ void ldsm2(uint32_t* r, uint32_t addr) {
    asm volatile("ldmatrix.sync.aligned.m8n8.x2.shared.b16 {%0,%1}, [%2];"
                 : "=r"(r[0]), "=r"(r[1]) : "r"(addr));
}

// D(16x8,f32) += A(16x16,bf16 row) * B(16x8,bf16 col)
__device__ __forceinline__ void mma16816(float* c, const uint32_t* a,
                                         const uint32_t* b) {
    asm volatile(
        "mma.sync.aligned.m16n8k16.row.col.f32.bf16.bf16.f32 "
        "{%0,%1,%2,%3}, {%4,%5,%6,%7}, {%8,%9}, {%0,%1,%2,%3};"
        : "+f"(c[0]), "+f"(c[1]), "+f"(c[2]), "+f"(c[3])
        : "r"(a[0]), "r"(a[1]), "r"(a[2]), "r"(a[3]), "r"(b[0]), "r"(b[1]));
}

__device__ __forceinline__ __nv_bfloat162 split_hi(float a, float b) {
    __nv_bfloat162 r; r.x = __float2bfloat16(a); r.y = __float2bfloat16(b);
    return r;
}
__device__ __forceinline__ __nv_bfloat162 split_lo(float a, float b,
                                                   __nv_bfloat162 h) {
    __nv_bfloat162 r;
    r.x = __float2bfloat16(a - __bfloat162float(h.x));
    r.y = __float2bfloat16(b - __bfloat162float(h.y));
    return r;
}

// ===================== split kernels =======================================
__global__ __launch_bounds__(256)
void split3_bf16(const float* __restrict__ s0, const float* __restrict__ s1,
                 const float* __restrict__ s2,
                 __nv_bfloat16* __restrict__ h, __nv_bfloat16* __restrict__ l,
                 int n_per)
{
    const float* s = (blockIdx.z == 0) ? s0 : ((blockIdx.z == 1) ? s1 : s2);
    size_t base = (size_t)blockIdx.z * n_per;
    size_t i4 = (size_t)blockIdx.x * 256 + threadIdx.x;
    float4 v = *reinterpret_cast<const float4*>(s + i4 * 4);

    __nv_bfloat162 h0 = split_hi(v.x, v.y), h1 = split_hi(v.z, v.w);
    __nv_bfloat162 l0 = split_lo(v.x, v.y, h0), l1 = split_lo(v.z, v.w, h1);
    *reinterpret_cast<__nv_bfloat162*>(h + base + i4 * 4)     = h0;
    *reinterpret_cast<__nv_bfloat162*>(h + base + i4 * 4 + 2) = h1;
    *reinterpret_cast<__nv_bfloat162*>(l + base + i4 * 4)     = l0;
    *reinterpret_cast<__nv_bfloat162*>(l + base + i4 * 4 + 2) = l1;
}

// W [K][N] fp32 row-major -> WhT/WlT [N][K] bf16 (K contiguous), z = which W.
__global__ __launch_bounds__(256)
void tsplit_w(const float* __restrict__ w0, const float* __restrict__ w1,
              const float* __restrict__ w2, const float* __restrict__ w3)
{
    __shared__ float t[32][33];
    const float* W = (blockIdx.z == 0) ? w0 : (blockIdx.z == 1) ? w1
                     : (blockIdx.z == 2) ? w2 : w3;
    size_t obase = (size_t)blockIdx.z * D_MODEL * D_MODEL;
    int n0 = blockIdx.x * 32, k0 = blockIdx.y * 32;
    int tx = threadIdx.x, ty = threadIdx.y;           // (32, 8)

#pragma unroll
    for (int i = 0; i < 4; i++)
        t[ty + 8 * i][tx] = W[(size_t)(k0 + ty + 8 * i) * D_MODEL + n0 + tx];
    __syncthreads();
#pragma unroll
    for (int i = 0; i < 4; i++) {
        float x = t[tx][ty + 8 * i];
        __nv_bfloat16 hb = __float2bfloat16(x);
        __nv_bfloat16 lb = __float2bfloat16(x - __bfloat162float(hb));
        size_t o = obase + (size_t)(n0 + ty + 8 * i) * D_MODEL + k0 + tx;
        g_w_h[o] = hb;
        g_w_l[o] = lb;
    }
}

// ===================== mma.sync bf16x2 GEMM tile ===========================
#define BK     32
#define PADK   40
#define TEN_H  (128 * PADK)
#define BUF_H  (4 * TEN_H)
#define TC_SMEM_BYTES (2 * BUF_H * 2)     // 81920 B

__device__ __forceinline__ void tc_gemm_tile(
    const __nv_bfloat16* __restrict__ Ah, const __nv_bfloat16* __restrict__ Al,
    const __nv_bfloat16* __restrict__ Bh, const __nv_bfloat16* __restrict__ Bl,
    const float* __restrict__ bias, float* __restrict__ C,
    __nv_bfloat16* __restrict__ Ch, __nv_bfloat16* __restrict__ Cl,
    int mrow0, int ncol0)
{
    extern __shared__ __nv_bfloat16 tc_sm[];
    const uint32_t smem_base = smem_to_u32(tc_sm);
    const int tid  = threadIdx.x;
    const int wid  = tid >> 5;
    const int lane = tid & 31;
    const int warp_m = wid >> 2;
    const int warp_n = wid & 3;

    const __nv_bfloat16* src[4] = {
        Ah + (size_t)mrow0 * D_MODEL, Al + (size_t)mrow0 * D_MODEL,
        Bh + (size_t)ncol0 * D_MODEL, Bl + (size_t)ncol0 * D_MODEL };

    float acc[4][4][4];
#pragma unroll
    for (int mt = 0; mt < 4; mt++)
#pragma unroll
        for (int nt = 0; nt < 4; nt++)
#pragma unroll
            for (int e = 0; e < 4; e++) acc[mt][nt][e] = 0.f;

    auto load_chunk = [&](int ci, int buf) {
#pragma unroll
        for (int j = 0; j < 8; j++) {
            int u = tid + j * 256;
            int t = u >> 9;
            int idx = u & 511;
            int r = idx >> 2, c = idx & 3;
            const void* g = src[t] + (size_t)r * D_MODEL + ci * BK + c * 8;
            uint32_t s = smem_base +
                (uint32_t)(buf * BUF_H + t * TEN_H + r * PADK + c * 8) * 2;
            cp_async16(s, g);
        }
        cp_commit();
    };

    auto compute = [&](int buf) {
        const uint32_t b0 = smem_base + (uint32_t)(buf * BUF_H) * 2;
#pragma unroll
        for (int ks = 0; ks < 2; ks++) {
            uint32_t bh[4][2], bl[4][2];
#pragma unroll
            for (int nt = 0; nt < 4; nt++) {
                int L  = lane & 15;
                int rn = warp_n * 32 + nt * 8 + (L & 7);
                int ch = ks * 16 + ((L >> 3) & 1) * 8;
                uint32_t ab = b0 + (uint32_t)(2 * TEN_H + rn * PADK + ch) * 2;
                ldsm2(bh[nt], ab);
                ldsm2(bl[nt], ab + TEN_H * 2);
            }
#pragma unroll
            for (int mt = 0; mt < 4; mt++) {
                int rm = warp_m * 64 + mt * 16 + (lane & 15);
                int ch = ks * 16 + (lane >> 4) * 8;
                uint32_t aa = b0 + (uint32_t)(rm * PADK + ch) * 2;
                uint32_t ah4[4], al4[4];
                ldsm4(ah4, aa);
                ldsm4(al4, aa + TEN_H * 2);
#pragma unroll
                for (int nt = 0; nt < 4; nt++) {
                    mma16816(acc[mt][nt], ah4, bh[nt]);
                    mma16816(acc[mt][nt], ah4, bl[nt]);
                    mma16816(acc[mt][nt], al4, bh[nt]);
                }
            }
        }
    };

    load_chunk(0, 0);
    for (int ci = 0; ci < D_MODEL / BK; ci++) {
        if (ci < D_MODEL / BK - 1) {
            load_chunk(ci + 1, (ci + 1) & 1);
            cp_wait<1>();
        } else {
            cp_wait<0>();
        }
        __syncthreads();
        compute(ci & 1);
        __syncthreads();
    }

    const int gid = lane >> 2, tig = lane & 3;
#pragma unroll
    for (int mt = 0; mt < 4; mt++) {
#pragma unroll
        for (int nt = 0; nt < 4; nt++) {
            int row = mrow0 + warp_m * 64 + mt * 16 + gid;
            int col = ncol0 + warp_n * 32 + nt * 8 + tig * 2;
            float b0v = __ldg(&bias[col]);
            float b1v = __ldg(&bias[col + 1]);
            float c0 = acc[mt][nt][0] + b0v, c1 = acc[mt][nt][1] + b1v;
            float c2 = acc[mt][nt][2] + b0v, c3 = acc[mt][nt][3] + b1v;
            float2 o1; o1.x = c0; o1.y = c1;
            float2 o2; o2.x = c2; o2.y = c3;
            *reinterpret_cast<float2*>(&C[(size_t)row * D_MODEL + col]) = o1;
            *reinterpret_cast<float2*>(&C[(size_t)(row + 8) * D_MODEL + col]) = o2;
            if (Ch) {                     // also emit split bf16 (Q/K paths)
                __nv_bfloat162 h1 = split_hi(c0, c1);
                __nv_bfloat162 h2 = split_hi(c2, c3);
                *reinterpret_cast<__nv_bfloat162*>(
                    &Ch[(size_t)row * D_MODEL + col]) = h1;
                *reinterpret_cast<__nv_bfloat162*>(
                    &Ch[(size_t)(row + 8) * D_MODEL + col]) = h2;
                *reinterpret_cast<__nv_bfloat162*>(
                    &Cl[(size_t)row * D_MODEL + col]) = split_lo(c0, c1, h1);
                *reinterpret_cast<__nv_bfloat162*>(
                    &Cl[(size_t)(row + 8) * D_MODEL + col]) = split_lo(c2, c3, h2);
            }
        }
    }
}

__global__ __launch_bounds__(256)
void tc_gemm_qkv(const float* __restrict__ bq, const float* __restrict__ bk,
                 const float* __restrict__ bv)
{
    const int z = blockIdx.z;
    const size_t aoff = (size_t)z * MROWS * D_MODEL;
    const size_t woff = (size_t)z * D_MODEL * D_MODEL;
    const float* bias = (z == 0) ? bq : (z == 1) ? bk : bv;
    float* C = g_f32 + (size_t)z * MROWS * D_MODEL;
    __nv_bfloat16* Ch = (z == 0) ? g_q_h : (z == 1) ? g_k_h : nullptr;
    __nv_bfloat16* Cl = (z == 0) ? g_q_l : (z == 1) ? g_k_l : nullptr;
    tc_gemm_tile(g_a_h + aoff, g_a_l + aoff, g_w_h + woff, g_w_l + woff,
                 bias, C, Ch, Cl, blockIdx.y * 128, blockIdx.x * 128);
}

__global__ __launch_bounds__(256)
void tc_gemm_out(const float* __restrict__ bo, float* __restrict__ out)
{
    const size_t woff = 3u * D_MODEL * D_MODEL;
    tc_gemm_tile(g_c_h, g_c_l, g_w_h + woff, g_w_l + woff,
                 bo, out, nullptr, nullptr, blockIdx.y * 128, blockIdx.x * 128);
}

// ==================== fused attention ======================================
// Phase 1: S = Q K^T via mma.sync split bf16. Phases 2/3 identical to R4.
#define ROWS   16
#define CHUNK  256
#define KPAD   68                         // fp32 V rows (floats)
#define KPAD2  72                         // bf16 split rows (halves; 144B)
#define SPAD   2049

#define S_BYTES   (ROWS * SPAD * 4)                 // 131136
#define KH_OFF    S_BYTES                           // [256][72] bf16
#define KL_OFF    (KH_OFF + CHUNK * KPAD2 * 2)      // +36864
#define V_OFF     S_BYTES                           // aliases K region (fp32)
#define QH_OFF    (KH_OFF + 2 * CHUNK * KPAD2 * 2)  // 204864
#define QL_OFF    (QH_OFF + ROWS * KPAD2 * 2)       // +2304
#define ATTN_SMEM_BYTES (QL_OFF + ROWS * KPAD2 * 2) // 209472

__global__ __launch_bounds__(512, 1)
void attn_fused(const __nv_bfloat16* __restrict__ Qh,
                const __nv_bfloat16* __restrict__ Ql,
                const __nv_bfloat16* __restrict__ Kh,
                const __nv_bfloat16* __restrict__ Kl,
                const float* __restrict__ V, float* __restrict__ Wout,
                float* __restrict__ Ctx)
{
    extern __shared__ float sm[];
    float* s_sm = sm;
    char*  smc  = reinterpret_cast<char*>(sm);
    const uint32_t smem_u32 = smem_to_u32(sm);

    const int tid = threadIdx.x;
    const int qb  = blockIdx.x;
    const int h   = blockIdx.y;
    const int b   = blockIdx.z;
    const int s0  = qb * ROWS;
    const int lane = tid & 31;

    const size_t headoff = (size_t)b * S_LEN * D_MODEL + (size_t)h * DK;
    const __nv_bfloat16* Qhh = Qh + headoff;
    const __nv_bfloat16* Qlh = Ql + headoff;
    const __nv_bfloat16* Khh = Kh + headoff;
    const __nv_bfloat16* Klh = Kl + headoff;
    const float* Vh = V + headoff;

    // ---- stage split Q [16][64] -> smem [16][72] ----
    {
        int t = tid >> 8;                 // 0: hi, 1: lo
        int i = tid & 255;
        int r = i >> 4, c4 = (i & 15) * 4;
        const __nv_bfloat16* g = (t ? Qlh : Qhh) + (size_t)(s0 + r) * D_MODEL + c4;
        uint2 v2 = *reinterpret_cast<const uint2*>(g);
        *reinterpret_cast<uint2*>(smc + (t ? QL_OFF : QH_OFF) +
                                  (r * KPAD2 + c4) * 2) = v2;
    }
    __syncthreads();

    // ---- hoist Q fragments (A operand, shared across warps) ----
    uint32_t qh4[4][4], ql4[4][4];
    {
        int rm = lane & 15;
        int cofs = (lane >> 4) * 8;
#pragma unroll
        for (int ks = 0; ks < 4; ks++) {
            int ch = ks * 16 + cofs;
            ldsm4(qh4[ks], smem_u32 + QH_OFF + (rm * KPAD2 + ch) * 2);
            ldsm4(ql4[ks], smem_u32 + QL_OFF + (rm * KPAD2 + ch) * 2);
        }
    }

    // ---- Phase 1: scores via mma ----
    const int wq  = tid >> 5;             // warp 0..15 -> 16 keys each
    const int gid = lane >> 2, tig = lane & 3;
    for (int ci = 0; ci < S_LEN / CHUNK; ci++) {
        // load split K chunk [256][64] -> smem [256][72] x2
#pragma unroll
        for (int j = 0; j < 8; j++) {
            int u = tid + j * 512;        // 0..4095
            int t = u >> 11;              // 0: hi, 1: lo
            int idx = u & 2047;
            int key = idx >> 3, c8 = (idx & 7) * 8;
            const __nv_bfloat16* g = (t ? Klh : Khh) +
                (size_t)(ci * CHUNK + key) * D_MODEL + c8;
            cp_async16(smem_u32 + (t ? KL_OFF : KH_OFF) +
                       (key * KPAD2 + c8) * 2, g);
        }
        cp_commit();
        cp_wait<0>();
        __syncthreads();

#pragma unroll
        for (int nf = 0; nf < 2; nf++) {
            float sacc[4] = {0.f, 0.f, 0.f, 0.f};
            int L  = lane & 15;
            int rn = wq * 16 + nf * 8 + (L & 7);
            int cofs = ((L >> 3) & 1) * 8;
#pragma unroll
            for (int ks = 0; ks < 4; ks++) {
                int ch = ks * 16 + cofs;
                uint32_t bh2[2], bl2[2];
                ldsm2(bh2, smem_u32 + KH_OFF + (rn * KPAD2 + ch) * 2);
                ldsm2(bl2, smem_u32 + KL_OFF + (rn * KPAD2 + ch) * 2);
                mma16816(sacc, qh4[ks], bh2);
                mma16816(sacc, qh4[ks], bl2);
                mma16816(sacc, ql4[ks], bh2);
            }
            int col = ci * CHUNK + wq * 16 + nf * 8 + tig * 2;
            s_sm[gid * SPAD + col]           = sacc[0] * 0.125f;
            s_sm[gid * SPAD + col + 1]       = sacc[1] * 0.125f;
            s_sm[(gid + 8) * SPAD + col]     = sacc[2] * 0.125f;
            s_sm[(gid + 8) * SPAD + col + 1] = sacc[3] * 0.125f;
        }
        __syncthreads();                  // guard K smem overwrite
    }

    // ---- Phase 2: softmax, one warp per row (identical to R4) ----
    {
        const int wrow = tid >> 5;
        float* srow = &s_sm[wrow * SPAD];

        float m = -1e30f;
#pragma unroll
        for (int j = 0; j < S_LEN / 32; j++) m = fmaxf(m, srow[lane + 32 * j]);
#pragma unroll
        for (int o = 16; o > 0; o >>= 1) m = fmaxf(m, __shfl_xor_sync(0xffffffffu, m, o));

        float z = 0.f;
#pragma unroll
        for (int j = 0; j < S_LEN / 32; j++) {
            float e = __expf(srow[lane + 32 * j] - m);
            srow[lane + 32 * j] = e;
            z += e;
        }
#pragma unroll
        for (int o = 16; o > 0; o >>= 1) z += __shfl_xor_sync(0xffffffffu, z, o);
        float invz = 1.f / z;

        float* wout = Wout + ((((size_t)b * NH + h) * S_LEN) + s0 + wrow) * S_LEN;
#pragma unroll
        for (int j = 0; j < S_LEN / 32; j++) {
            float wv = srow[lane + 32 * j] * invz;
            srow[lane + 32 * j] = wv;
            wout[lane + 32 * j] = wv;
        }
    }
    __syncthreads();

    // ---- Phase 3: PV (identical to R4; V chunk aliases K region) ----
    float* v_sm = reinterpret_cast<float*>(smc + V_OFF);
    const int row = tid & 15;
    const int cg  = tid >> 4;

    float acc[64];
#pragma unroll
    for (int d = 0; d < 64; d++) acc[d] = 0.f;

    for (int ci = 0; ci < S_LEN / CHUNK; ci++) {
#pragma unroll
        for (int it = 0; it < 8; it++) {
            int l  = tid + it * 512;
            int c  = l >> 4;
            int d4 = (l & 15) << 2;
            float4 vv = *reinterpret_cast<const float4*>(
                &Vh[(size_t)(ci * CHUNK + c) * D_MODEL + d4]);
            *reinterpret_cast<float4*>(&v_sm[c * KPAD + d4]) = vv;
        }
        __syncthreads();
#pragma unroll
        for (int cc = 0; cc < CHUNK / 32; cc++) {
            int c = (cc << 5) + cg;
            float wv = s_sm[row * SPAD + ci * CHUNK + c];
            const float4* vp = reinterpret_cast<const float4*>(&v_sm[c * KPAD]);
#pragma unroll
            for (int d4 = 0; d4 < 16; d4++) {
                float4 vv = vp[d4];
                acc[4 * d4 + 0] += wv * vv.x;
                acc[4 * d4 + 1] += wv * vv.y;
                acc[4 * d4 + 2] += wv * vv.z;
                acc[4 * d4 + 3] += wv * vv.w;
            }
        }
        __syncthreads();
    }

    float* sred = s_sm;
#pragma unroll
    for (int d = 0; d < 64; d++) sred[d * 512 + tid] = acc[d];
    __syncthreads();
    {
        int row_o = tid & 15;
        int d0    = (tid >> 4) << 1;
        float s0v = 0.f, s1v = 0.f;
#pragma unroll
        for (int g = 0; g < 32; g++) {
            s0v += sred[(d0 + 0) * 512 + g * 16 + row_o];
            s1v += sred[(d0 + 1) * 512 + g * 16 + row_o];
        }
        float2 o; o.x = s0v; o.y = s1v;
        *reinterpret_cast<float2*>(
            &Ctx[((size_t)b * S_LEN + s0 + row_o) * D_MODEL + h * DK + d0]) = o;
    }
}

// ============================== launch =====================================
extern "C" void kernel_launch(void* const* d_in, const int* in_sizes, int n_in,
                              void* d_out, int out_size)
{
    (void)in_sizes; (void)n_in; (void)out_size;

    const float* query = (const float*)d_in[0];
    const float* key   = (const float*)d_in[1];
    const float* value = (const float*)d_in[2];
    const float* Wq    = (const float*)d_in[3];
    const float* bq    = (const float*)d_in[4];
    const float* Wk    = (const float*)d_in[5];
    const float* bk    = (const float*)d_in[6];
    const float* Wv    = (const float*)d_in[7];
    const float* bv    = (const float*)d_in[8];
    const float* Wo    = (const float*)d_in[9];
    const float* bo    = (const float*)d_in[10];

    float* out  = (float*)d_out;
    float* attw = out + (size_t)B_SZ * S_LEN * D_MODEL;

    float* f32s = nullptr;
    cudaGetSymbolAddress((void**)&f32s, g_f32);
    float* gV = f32s + 2u * MROWS * D_MODEL;
    float* gC = f32s + 3u * MROWS * D_MODEL;

    __nv_bfloat16 *ah, *al, *ch, *cl, *qh, *ql, *kh, *kl;
    cudaGetSymbolAddress((void**)&ah, g_a_h);
    cudaGetSymbolAddress((void**)&al, g_a_l);
    cudaGetSymbolAddress((void**)&ch, g_c_h);
    cudaGetSymbolAddress((void**)&cl, g_c_l);
    cudaGetSymbolAddress((void**)&qh, g_q_h);
    cudaGetSymbolAddress((void**)&ql, g_q_l);
    cudaGetSymbolAddress((void**)&kh, g_k_h);
    cudaGetSymbolAddress((void**)&kl, g_k_l);

    cudaFuncSetAttribute(attn_fused, cudaFuncAttributeMaxDynamicSharedMemorySize,
                         ATTN_SMEM_BYTES);
    cudaFuncSetAttribute(tc_gemm_qkv, cudaFuncAttributeMaxDynamicSharedMemorySize,
                         TC_SMEM_BYTES);
    cudaFuncSetAttribute(tc_gemm_out, cudaFuncAttributeMaxDynamicSharedMemorySize,
                         TC_SMEM_BYTES);

    const int n_per = MROWS * D_MODEL;                       // 4.19M

    // 1. split inputs -> bf16 hi/lo (GEMM A operands)
    split3_bf16<<<dim3(n_per / 1024, 1, 3), 256>>>(query, key, value, ah, al, n_per);
    // 2. transpose + split weights
    tsplit_w<<<dim3(32, 32, 4), dim3(32, 8)>>>(Wq, Wk, Wv, Wo);
    // 3. QKV projections on HMMA; epilogue emits split Q/K
    tc_gemm_qkv<<<dim3(8, 32, 3), 256, TC_SMEM_BYTES>>>(bq, bk, bv);
    // 4. fused attention (phase 1 on HMMA)
    attn_fused<<<dim3(S_LEN / ROWS, NH, B_SZ), 512, ATTN_SMEM_BYTES>>>(
        qh, ql, kh, kl, gV, attw, gC);
    // 5. split context
    split3_bf16<<<dim3(n_per / 1024, 1, 1), 256>>>(gC, gC, gC, ch, cl, n_per);
    // 6. output projection on HMMA
    tc_gemm_out<<<dim3(8, 32, 1), 256, TC_SMEM_BYTES>>>(bo, out);
}